// round 6
// baseline (speedup 1.0000x reference)
#include <cuda_runtime.h>
#include <cstdint>

#define HH 128
#define WW 128
#define CHN 64
#define OCH 64
#define BATCH 4

#define YP 136          // y smem pitch (floats); 136 % 32 == 8 -> conflict-free frags

#define Y_FLOATS  (4 * 32 * YP)                 // 17408
#define FA_FLOATS (4 * YP)                      // 544
#define OFF_Y  0
#define OFF_FA (OFF_Y + Y_FLOATS)
#define OFF_BI (OFF_FA + FA_FLOATS)
#define SMEM_FLOATS (OFF_BI + 64)
#define SMEM_BYTES  (SMEM_FLOATS * 4)           // ~72 KB

__device__ __forceinline__ float to_tf32(float x) {
    float r; asm("cvt.rn.tf32.f32 %0, %1;" : "=f"(r) : "f"(x)); return r;
}

__device__ __forceinline__ void mma_tf32(float* d, const uint32_t* a, uint32_t b0, uint32_t b1) {
    asm volatile(
        "mma.sync.aligned.m16n8k8.row.col.f32.tf32.tf32.f32 "
        "{%0,%1,%2,%3}, {%4,%5,%6,%7}, {%8,%9}, {%0,%1,%2,%3};\n"
        : "+f"(d[0]), "+f"(d[1]), "+f"(d[2]), "+f"(d[3])
        : "r"(a[0]), "r"(a[1]), "r"(a[2]), "r"(a[3]), "r"(b0), "r"(b1));
}

// ---- prepacked weight PAIRS for direct b-fragment LDG.64:
// g_w2[(((h*9+t)*4+cq)*4+tq)*64 + n] = { tf32(W[n][h*32+cq*8+tq][t]),
//                                        tf32(W[n][h*32+cq*8+tq+4][t]) }
__device__ float2 g_w2[2 * 9 * 4 * 4 * 64];   // 18432 pairs = all 36864 weights

__global__ void wt_prepack(const float* __restrict__ w) {
    int i = blockIdx.x * 256 + threadIdx.x;
    if (i >= 2 * 9 * 4 * 4 * 64) return;
    int n  = i & 63;
    int tq = (i >> 6) & 3;
    int cq = (i >> 8) & 3;
    int ht = i >> 10;            // 0..17
    int t  = ht % 9;
    int h  = ht / 9;
    int c0 = h * 32 + cq * 8 + tq;
    float v0 = w[(n * CHN + c0) * 9 + t];
    float v1 = w[(n * CHN + c0 + 4) * 9 + t];
    g_w2[i] = make_float2(to_tf32(v0), to_tf32(v1));
}

// ============================ main kernel ============================
// CTA = (batch, row-pair). M = 256 pixels (2 rows x 128), N = 64, K = 576.
// 8 warps; warp tile 32(px) x 64(o). Weights come straight from L1 via
// prepacked LDG.64 pairs -> no w_s, no per-tap barrier: only 4 barriers total.

__global__ __launch_bounds__(256, 2)
void conv_mma(const float* __restrict__ x,
              const float* __restrict__ alpha,
              const float* __restrict__ bias,
              const float* __restrict__ pa,
              const float* __restrict__ pb,
              const float* __restrict__ pc,
              float* __restrict__ out)
{
    extern __shared__ float sm[];
    float* y_s  = sm + OFF_Y;    // [4 imgrows][32 c][YP]
    float* fa_s = sm + OFF_FA;   // [4 imgrows][YP]
    float* bi_s = sm + OFF_BI;   // [64]

    const int tid  = threadIdx.x;
    const int warp = tid >> 5;
    const int lane = tid & 31;
    const int qid  = lane >> 2;  // 0..7
    const int tq   = lane & 3;   // 0..3

    const int rp = blockIdx.x;   // row pair 0..63
    const int b  = blockIdx.y;   // batch
    const int r0 = 2 * rp;

    const int lr  = warp >> 2;          // which of the 2 output rows
    const int px0 = (warp & 3) * 32;    // pixel block start

    // ---- f(alpha) for imgrows r0-1 .. r0+2, padded (col j -> image col j-1)
    {
        const float A = __ldg(pa), Bq = __ldg(pb), Cq = __ldg(pc);
        const float* ap = alpha + b * HH * WW;
        for (int i = tid; i < 4 * YP; i += 256) {
            int ir = i / YP, j = i - ir * YP;
            int gy = r0 - 1 + ir, gx = j - 1;
            float v = 0.0f;
            if ((unsigned)gy < HH && (unsigned)gx < WW) {
                float t = __ldg(ap + gy * WW + gx);
                v = (A * t + Bq) * t + Cq;
            }
            fa_s[i] = v;
        }
    }
    if (tid < 64) bi_s[tid] = __ldg(bias + tid);

    float d[2][8][4];
    #pragma unroll
    for (int mi = 0; mi < 2; mi++)
        #pragma unroll
        for (int j = 0; j < 8; j++)
            #pragma unroll
            for (int r = 0; r < 4; r++) d[mi][j][r] = 0.0f;

    // per-thread a-fragment base: + kt*32*YP + lt + cq*8*YP + mi*16
    const int abase = (lr * 32 + tq) * YP + px0 + qid;

    #pragma unroll 1
    for (int h = 0; h < 2; h++) {
        __syncthreads();   // fa_s ready (h=0) / previous half's readers done (h=1)

        // ---- y half: premultiplied + tf32-rounded, rows r0-1..r0+2, 32 channels
        #pragma unroll 1
        for (int e = tid; e < 4 * 32 * 128; e += 256) {
            int px = e & 127;
            int c  = (e >> 7) & 31;
            int ir = e >> 12;
            int gy = r0 - 1 + ir;
            float v = 0.0f;
            if ((unsigned)gy < HH)
                v = __ldg(x + (((b * CHN + h * 32 + c) * HH) + gy) * WW + px);
            y_s[(ir * 32 + c) * YP + 1 + px] = to_tf32(v * fa_s[ir * YP + 1 + px]);
        }
        if (tid < 128) {            // zero pad left/right columns
            y_s[tid * YP + 0]   = 0.0f;
            y_s[tid * YP + 129] = 0.0f;
        }
        __syncthreads();

        // ---- 9 taps, NO barriers inside: warps drift freely across the half
        #pragma unroll 1
        for (int t = 0; t < 9; t++) {
            const int kt = t / 3, lt = t - 3 * kt;
            const float* ya = y_s + abase + kt * (32 * YP) + lt;
            const float2* wt0 = g_w2 + ((h * 9 + t) * 16 + tq) * 64 + qid;

            #pragma unroll
            for (int cq = 0; cq < 4; cq++) {
                // b-fragments: one LDG.64 pair per j, L1-resident
                const float2* wq = wt0 + (cq * 4) * 64;
                float2 bv[8];
                #pragma unroll
                for (int j = 0; j < 8; j++) bv[j] = __ldg(wq + j * 8);

                // a-fragments from smem (layout verified in R4)
                const float* yq = ya + cq * (8 * YP);
                uint32_t a[2][4];
                #pragma unroll
                for (int mi = 0; mi < 2; mi++) {
                    const float* p = yq + mi * 16;
                    a[mi][0] = __float_as_uint(p[0]);           // (row,   k)
                    a[mi][1] = __float_as_uint(p[8]);           // (row+8, k)
                    a[mi][2] = __float_as_uint(p[4 * YP]);      // (row,   k+4)
                    a[mi][3] = __float_as_uint(p[4 * YP + 8]);  // (row+8, k+4)
                }
                #pragma unroll
                for (int mi = 0; mi < 2; mi++)
                    #pragma unroll
                    for (int j = 0; j < 8; j++)
                        mma_tf32(d[mi][j], a[mi],
                                 __float_as_uint(bv[j].x), __float_as_uint(bv[j].y));
            }
        }
    }

    // ---- epilogue: C frag c0,c1 = (row=qid, o=2tq, 2tq+1); c2,c3 = row+8
    const int imgrow = r0 + lr;
    #pragma unroll
    for (int j = 0; j < 8; j++) {
        const int o0 = j * 8 + 2 * tq;
        const float b0v = bi_s[o0], b1v = bi_s[o0 + 1];
        float* p0 = out + (((b * OCH + o0) * HH) + imgrow) * WW;
        #pragma unroll
        for (int mi = 0; mi < 2; mi++) {
            const int px = px0 + mi * 16 + qid;
            p0[px]               = d[mi][j][0] + b0v;
            p0[HH * WW + px]     = d[mi][j][1] + b1v;
            p0[px + 8]           = d[mi][j][2] + b0v;
            p0[HH * WW + px + 8] = d[mi][j][3] + b1v;
        }
    }
}

// ============================ launch ============================
extern "C" void kernel_launch(void* const* d_in, const int* in_sizes, int n_in,
                              void* d_out, int out_size)
{
    const float* x     = (const float*)d_in[0];
    const float* alpha = (const float*)d_in[1];
    const float* wgt   = (const float*)d_in[2];
    const float* bias  = (const float*)d_in[3];
    const float* pa    = (const float*)d_in[4];
    const float* pb    = (const float*)d_in[5];
    const float* pc    = (const float*)d_in[6];
    float* out = (float*)d_out;

    wt_prepack<<<(2 * 9 * 4 * 4 * 64 + 255) / 256, 256>>>(wgt);

    cudaFuncSetAttribute(conv_mma,
                         cudaFuncAttributeMaxDynamicSharedMemorySize, SMEM_BYTES);
    dim3 grid(HH / 2, BATCH);   // 64 row-pairs x 4 batches = 256 CTAs, single wave
    conv_mma<<<grid, 256, SMEM_BYTES>>>(x, alpha, bias, pa, pb, pc, out);
}

// round 7
// speedup vs baseline: 1.0947x; 1.0947x over previous
#include <cuda_runtime.h>
#include <cstdint>

#define HH 128
#define WW 128
#define CHN 64
#define OCH 64
#define BATCH 4

#define RPB 4            // image rows per CTA -> M = 512
#define YPX 130          // padded pixel count per image row
#define YPITCH 36        // floats per pixel (32 ch + pad); 36%32==4 -> a-LDS conflict-free
#define WPITCH 72        // float2 per (t,cq,tq) row; phase covers all 32 banks

#define Y_FLOATS  (6 * YPX * YPITCH)        // 28080
#define W2_FLOAT2 (9 * 4 * 4 * WPITCH)      // 10368 per half
#define W2_FLOATS (W2_FLOAT2 * 2)           // 20736
#define FA_FLOATS (6 * YPX)                 // 780

#define OFF_Y  0
#define OFF_W2 Y_FLOATS                     // 28080 (byte off 112320, 16B-aligned)
#define OFF_FA (OFF_W2 + W2_FLOATS)         // 48816
#define OFF_BI (OFF_FA + FA_FLOATS)         // 49596
#define SMEM_FLOATS (OFF_BI + 64)
#define SMEM_BYTES  (SMEM_FLOATS * 4)       // 198640 B -> 1 CTA/SM

__device__ __forceinline__ float to_tf32(float x) {
    float r; asm("cvt.rn.tf32.f32 %0, %1;" : "=f"(r) : "f"(x)); return r;
}

__device__ __forceinline__ void mma_tf32(float* d, const uint32_t* a, uint32_t b0, uint32_t b1) {
    asm volatile(
        "mma.sync.aligned.m16n8k8.row.col.f32.tf32.tf32.f32 "
        "{%0,%1,%2,%3}, {%4,%5,%6,%7}, {%8,%9}, {%0,%1,%2,%3};\n"
        : "+f"(d[0]), "+f"(d[1]), "+f"(d[2]), "+f"(d[3])
        : "r"(a[0]), "r"(a[1]), "r"(a[2]), "r"(a[3]), "r"(b0), "r"(b1));
}

// ---- prepacked weight pairs, per half, smem-image layout:
// g_w2[h*W2_FLOAT2 + ((t*4+cq)*4+tq)*WPITCH + n] =
//   { tf32(W[n][h*32+cq*8+tq][t]), tf32(W[n][h*32+cq*8+tq+4][t]) }
__device__ __align__(16) float2 g_w2[2 * W2_FLOAT2];

__global__ void wt_prepack(const float* __restrict__ w) {
    int i = blockIdx.x * 256 + threadIdx.x;
    if (i >= 2 * 9 * 4 * 4 * 64) return;
    int n  = i & 63;
    int tq = (i >> 6) & 3;
    int cq = (i >> 8) & 3;
    int ht = i >> 10;
    int t  = ht % 9;
    int h  = ht / 9;
    int c0 = h * 32 + cq * 8 + tq;
    float v0 = w[(n * CHN + c0) * 9 + t];
    float v1 = w[(n * CHN + c0 + 4) * 9 + t];
    g_w2[h * W2_FLOAT2 + ((t * 4 + cq) * 4 + tq) * WPITCH + n] =
        make_float2(to_tf32(v0), to_tf32(v1));
}

// ============================ main kernel ============================
// CTA = (batch, 4-row band). M=512 px, N=64, K=576.
// 8 warps, warp tile 64px x 64o (4 m16 x 8 n8), 128 accum regs/thread.
// Whole channel-half resident in smem (y tile + all 9 taps of weights):
// only 4 __syncthreads total; tap loop is barrier-free.

__global__ __launch_bounds__(256, 1)
void conv_mma(const float* __restrict__ x,
              const float* __restrict__ alpha,
              const float* __restrict__ bias,
              const float* __restrict__ pa,
              const float* __restrict__ pb,
              const float* __restrict__ pc,
              float* __restrict__ out)
{
    extern __shared__ float sm[];
    float*  y_s  = sm + OFF_Y;    // [6 ir][130 pxpad][YPITCH]
    float2* w2_s = (float2*)(sm + OFF_W2);
    float*  fa_s = sm + OFF_FA;   // [6 ir][130]
    float*  bi_s = sm + OFF_BI;

    const int tid  = threadIdx.x;
    const int warp = tid >> 5;
    const int lane = tid & 31;
    const int qid  = lane >> 2;   // 0..7
    const int tq   = lane & 3;    // 0..3

    const int b  = blockIdx.y;
    const int r0 = RPB * blockIdx.x;      // first output image row

    const int lr  = warp >> 1;            // image row within band (0..3)
    const int px0 = (warp & 1) * 64;      // pixel block start

    // ---- f(alpha), bias, pad-zeros (written once; fill never touches pads)
    {
        const float A = __ldg(pa), Bq = __ldg(pb), Cq = __ldg(pc);
        const float* ap = alpha + b * HH * WW;
        for (int i = tid; i < 6 * YPX; i += 256) {
            int ir = i / YPX, j = i - ir * YPX;
            int gy = r0 - 1 + ir, gx = j - 1;
            float v = 0.0f;
            if ((unsigned)gy < HH && (unsigned)gx < WW) {
                float t = __ldg(ap + gy * WW + gx);
                v = (A * t + Bq) * t + Cq;
            }
            fa_s[i] = v;
        }
        for (int i = tid; i < 6 * 2 * 32; i += 256) {   // zero pxpad 0 and 129
            int c  = i & 31;
            int jj = (i >> 5) & 1;
            int ir = i >> 6;
            y_s[(ir * YPX + (jj ? 129 : 0)) * YPITCH + c] = 0.0f;
        }
        if (tid < 64) bi_s[tid] = __ldg(bias + tid);
    }

    float d[4][8][4];
    #pragma unroll
    for (int mi = 0; mi < 4; mi++)
        #pragma unroll
        for (int j = 0; j < 8; j++)
            #pragma unroll
            for (int r = 0; r < 4; r++) d[mi][j][r] = 0.0f;

    const int px_l = lane & 7;   // fill mapping: 8 px x 4 c per warp-iter
    const int c_l  = lane >> 3;

    #pragma unroll 1
    for (int h = 0; h < 2; h++) {
        __syncthreads();   // fa/pads ready (h=0); prev half's readers done (h=1)

        // ---- weights for this half: linear float4 copy of prepacked image
        {
            const float4* src = (const float4*)(g_w2 + h * W2_FLOAT2);
            float4* dst = (float4*)w2_s;
            #pragma unroll 4
            for (int i = tid; i < (W2_FLOAT2 * 2) / 4; i += 256) dst[i] = src[i];
        }

        // ---- y half: premultiplied + tf32-rounded. 768 warp-iters of 8px x 4c.
        #pragma unroll 1
        for (int I = warp; I < 6 * 16 * 8; I += 8) {
            int cb  = I & 7;
            int pxb = (I >> 3) & 15;
            int ir  = I >> 7;
            int px  = pxb * 8 + px_l;
            int c   = cb * 4 + c_l;
            int gy  = r0 - 1 + ir;
            float v = 0.0f;
            if ((unsigned)gy < HH)
                v = __ldg(x + (((b * CHN + h * 32 + c) * HH) + gy) * WW + px);
            y_s[(ir * YPX + 1 + px) * YPITCH + c] = to_tf32(v * fa_s[ir * YPX + 1 + px]);
        }
        __syncthreads();

        // ---- 9 taps, barrier-free
        #pragma unroll 1
        for (int t = 0; t < 9; t++) {
            const int kt = t / 3, lt = t - 3 * kt;
            const float*  ya = y_s + ((lr + kt) * YPX + px0 + lt + qid) * YPITCH + tq;
            const float2* wb = w2_s + (t * 16 + tq) * WPITCH + qid;

            #pragma unroll
            for (int cq = 0; cq < 4; cq++) {
                float2 bv[8];
                const float2* wq = wb + cq * 4 * WPITCH;
                #pragma unroll
                for (int j = 0; j < 8; j++) bv[j] = wq[j * 8];

                uint32_t a[4][4];
                #pragma unroll
                for (int mi = 0; mi < 4; mi++) {
                    const float* p = ya + (mi * 16) * YPITCH + cq * 8;
                    a[mi][0] = __float_as_uint(p[0]);                 // (px,   k)
                    a[mi][1] = __float_as_uint(p[8 * YPITCH]);        // (px+8, k)
                    a[mi][2] = __float_as_uint(p[4]);                 // (px,   k+4)
                    a[mi][3] = __float_as_uint(p[8 * YPITCH + 4]);    // (px+8, k+4)
                }
                #pragma unroll
                for (int mi = 0; mi < 4; mi++)
                    #pragma unroll
                    for (int j = 0; j < 8; j++)
                        mma_tf32(d[mi][j], a[mi],
                                 __float_as_uint(bv[j].x), __float_as_uint(bv[j].y));
            }
        }
    }

    // ---- epilogue (fragment map identical to verified R4)
    const int imgrow = r0 + lr;
    #pragma unroll
    for (int j = 0; j < 8; j++) {
        const int o0 = j * 8 + 2 * tq;
        const float b0v = bi_s[o0], b1v = bi_s[o0 + 1];
        float* p0 = out + (((b * OCH + o0) * HH) + imgrow) * WW;
        #pragma unroll
        for (int mi = 0; mi < 4; mi++) {
            const int px = px0 + mi * 16 + qid;
            p0[px]               = d[mi][j][0] + b0v;
            p0[HH * WW + px]     = d[mi][j][1] + b1v;
            p0[px + 8]           = d[mi][j][2] + b0v;
            p0[HH * WW + px + 8] = d[mi][j][3] + b1v;
        }
    }
}

// ============================ launch ============================
extern "C" void kernel_launch(void* const* d_in, const int* in_sizes, int n_in,
                              void* d_out, int out_size)
{
    const float* x     = (const float*)d_in[0];
    const float* alpha = (const float*)d_in[1];
    const float* wgt   = (const float*)d_in[2];
    const float* bias  = (const float*)d_in[3];
    const float* pa    = (const float*)d_in[4];
    const float* pb    = (const float*)d_in[5];
    const float* pc    = (const float*)d_in[6];
    float* out = (float*)d_out;

    wt_prepack<<<(2 * 9 * 4 * 4 * 64 + 255) / 256, 256>>>(wgt);

    cudaFuncSetAttribute(conv_mma,
                         cudaFuncAttributeMaxDynamicSharedMemorySize, SMEM_BYTES);
    dim3 grid(HH / RPB, BATCH);   // 32 x 4 = 128 CTAs, single wave at 1 CTA/SM
    conv_mma<<<grid, 256, SMEM_BYTES>>>(x, alpha, bias, pa, pb, pc, out);
}

// round 9
// speedup vs baseline: 2.1447x; 1.9591x over previous
#include <cuda_runtime.h>
#include <cstdint>

#define HH 128
#define WW 128
#define CHN 64
#define OCH 64
#define BATCH 4

#define CC 16            // channels per chunk (4 chunks)
#define YP 136           // y row pitch (floats); 136 % 32 == 8 -> conflict-free a-LDS
#define YOFF 4           // left pad: px p lives at YP-row offset 4+p (float4-aligned)

#define Y_FLOATS  (4 * CC * YP)             // 8704
#define W_FLOATS  (9 * CC * 64)             // 9216  (one chunk, all 9 taps)
#define FA_FLOATS (4 * YP)                  // 544
#define OFF_Y  0
#define OFF_W  Y_FLOATS                     // 8704
#define OFF_FA (OFF_W + W_FLOATS)           // 17920
#define OFF_BI (OFF_FA + FA_FLOATS)         // 18464
#define SMEM_FLOATS (OFF_BI + 64)
#define SMEM_BYTES  (SMEM_FLOATS * 4)       // 74112 B -> 2 CTAs/SM

__device__ __forceinline__ float to_tf32(float x) {
    float r; asm("cvt.rn.tf32.f32 %0, %1;" : "=f"(r) : "f"(x)); return r;
}

__device__ __forceinline__ void mma_tf32(float* d, const uint32_t* a, uint32_t b0, uint32_t b1) {
    asm volatile(
        "mma.sync.aligned.m16n8k8.row.col.f32.tf32.tf32.f32 "
        "{%0,%1,%2,%3}, {%4,%5,%6,%7}, {%8,%9}, {%0,%1,%2,%3};\n"
        : "+f"(d[0]), "+f"(d[1]), "+f"(d[2]), "+f"(d[3])
        : "r"(a[0]), "r"(a[1]), "r"(a[2]), "r"(a[3]), "r"(b0), "r"(b1));
}

// ---- prepacked weights: g_w3[chunk][tap][c(16)][64], bank-derotated:
// slot n' = (n + 8*c) & 63 holds tf32(W[n][chunk*16 + c][tap]).
// Read side: thread (qid,tq) fetches slot 8*((j+tq)&7)+qid  (all 32 banks).
__device__ __align__(16) float g_w3[4 * 9 * CC * 64];

__global__ void wt_prepack(const float* __restrict__ w) {
    int i = blockIdx.x * 256 + threadIdx.x;
    if (i >= 4 * 9 * CC * 64) return;
    int n  = i & 63;
    int c  = (i >> 6) & 15;
    int ct = i >> 10;            // chunk*9 + tap
    int t  = ct % 9;
    int ch = ct / 9;
    float v = w[(n * CHN + ch * CC + c) * 9 + t];
    g_w3[((ch * 9 + t) * CC + c) * 64 + ((n + 8 * c) & 63)] = to_tf32(v);
}

// ============================ main kernel ============================
// CTA = (batch, row-pair). M = 256 px, N = 64, K = 576 in 4 chunks of 16 ch.
// 8 warps, warp tile 32px x 64o (R4-verified fragment maps).
// Per chunk: one barrier pair around (w copy + y fill); the 9-tap MMA stream
// is barrier-free. 8 barriers total (vs R4's 18), still 16 warps/SM.

__global__ __launch_bounds__(256, 2)
void conv_mma(const float* __restrict__ x,
              const float* __restrict__ alpha,
              const float* __restrict__ bias,
              const float* __restrict__ pa,
              const float* __restrict__ pb,
              const float* __restrict__ pc,
              float* __restrict__ out)
{
    extern __shared__ float sm[];
    float* y_s  = sm + OFF_Y;    // [4 ir][16 c][YP], px at offset YOFF+px
    float* w_s  = sm + OFF_W;    // [9 t][16 c][64] derotated
    float* fa_s = sm + OFF_FA;   // [4 ir][YP], px at offset YOFF+px
    float* bi_s = sm + OFF_BI;

    const int tid  = threadIdx.x;
    const int warp = tid >> 5;
    const int lane = tid & 31;
    const int qid  = lane >> 2;  // 0..7
    const int tq   = lane & 3;   // 0..3

    const int rp = blockIdx.x;
    const int b  = blockIdx.y;
    const int r0 = 2 * rp;

    const int lr  = warp >> 2;          // output row within pair
    const int px0 = (warp & 3) * 32;    // pixel block

    // ---- f(alpha) (per source pixel), bias, y pad-zeros (written once)
    {
        const float A = __ldg(pa), Bq = __ldg(pb), Cq = __ldg(pc);
        const float* ap = alpha + b * HH * WW;
        for (int i = tid; i < 4 * 128; i += 256) {
            int ir = i >> 7, px = i & 127;
            int gy = r0 - 1 + ir;
            float v = 0.0f;
            if ((unsigned)gy < HH) {
                float t = __ldg(ap + gy * WW + px);
                v = (A * t + Bq) * t + Cq;
            }
            fa_s[ir * YP + YOFF + px] = v;
        }
        for (int i = tid; i < 64 * 8; i += 256) {     // zero y pads (never refilled)
            int r = i >> 3, o = i & 7;
            y_s[r * YP + (o < 4 ? o : 128 + o)] = 0.0f;
        }
        if (tid < 64) bi_s[tid] = __ldg(bias + tid);
    }

    float d[2][8][4];
    #pragma unroll
    for (int mi = 0; mi < 2; mi++)
        #pragma unroll
        for (int j = 0; j < 8; j++)
            #pragma unroll
            for (int r = 0; r < 4; r++) d[mi][j][r] = 0.0f;

    // derotated b-slot table (loop-invariant)
    int wo[8];
    #pragma unroll
    for (int j = 0; j < 8; j++) wo[j] = 8 * ((j + tq) & 7) + qid;

    #pragma unroll 1
    for (int ch = 0; ch < 4; ch++) {
        __syncthreads();   // pads/fa ready (ch=0); prev chunk's readers done

        // ---- weights: linear float4 copy of this chunk's 9-tap derotated image
        {
            const float4* src = (const float4*)(g_w3 + ch * W_FLOATS);
            float4* dst = (float4*)w_s;
            #pragma unroll
            for (int i = 0; i < 9; i++) dst[tid + i * 256] = src[tid + i * 256];
        }
        // ---- y fill: warp = one (ir,c) row per iter, float4 px-coalesced
        #pragma unroll
        for (int it = 0; it < 8; it++) {
            int r  = warp + it * 8;           // 0..63
            int ir = r >> 4, c = r & 15;
            int gy = r0 - 1 + ir;
            int px = lane * 4;
            float4 v = make_float4(0.f, 0.f, 0.f, 0.f);
            if ((unsigned)gy < HH)
                v = *(const float4*)(x + (((b * CHN + ch * CC + c) * HH) + gy) * WW + px);
            float4 f = *(const float4*)(fa_s + ir * YP + YOFF + px);
            float4 yv = make_float4(to_tf32(v.x * f.x), to_tf32(v.y * f.y),
                                    to_tf32(v.z * f.z), to_tf32(v.w * f.w));
            *(float4*)(y_s + (ir * CC + c) * YP + YOFF + px) = yv;
        }
        __syncthreads();

        // ---- 9 taps, barrier-free
        #pragma unroll 1
        for (int t = 0; t < 9; t++) {
            const int kt = t / 3, lt = t - 3 * kt;
            const float* arow = y_s + ((lr + kt) * CC + tq) * YP + YOFF + px0 + lt - 1 + qid;
            const float* wrow = w_s + (t * CC + tq) * 64;

            #pragma unroll
            for (int cq = 0; cq < 2; cq++) {
                const float* wr = wrow + cq * 512;     // + cq*8 rows
                float bv0[8], bv1[8];
                #pragma unroll
                for (int j = 0; j < 8; j++) {
                    bv0[j] = wr[wo[j]];                // B[k  ][n]
                    bv1[j] = wr[256 + (wo[j] ^ 32)];   // B[k+4][n] (row +4, slot +32 mod 64)
                }
                const float* ap = arow + cq * (8 * YP);
                uint32_t a[2][4];
                #pragma unroll
                for (int mi = 0; mi < 2; mi++) {
                    const float* p = ap + mi * 16;
                    a[mi][0] = __float_as_uint(p[0]);            // (m,   k)
                    a[mi][1] = __float_as_uint(p[8]);            // (m+8, k)
                    a[mi][2] = __float_as_uint(p[4 * YP]);       // (m,   k+4)
                    a[mi][3] = __float_as_uint(p[4 * YP + 8]);   // (m+8, k+4)
                }
                #pragma unroll
                for (int mi = 0; mi < 2; mi++)
                    #pragma unroll
                    for (int j = 0; j < 8; j++)
                        mma_tf32(d[mi][j], a[mi],
                                 __float_as_uint(bv0[j]), __float_as_uint(bv1[j]));
            }
        }
    }

    // ---- epilogue (R4-verified fragment map)
    const int imgrow = r0 + lr;
    #pragma unroll
    for (int j = 0; j < 8; j++) {
        const int o0 = j * 8 + 2 * tq;
        const float b0v = bi_s[o0], b1v = bi_s[o0 + 1];
        float* p0 = out + (((b * OCH + o0) * HH) + imgrow) * WW;
        #pragma unroll
        for (int mi = 0; mi < 2; mi++) {
            const int px = px0 + mi * 16 + qid;
            p0[px]               = d[mi][j][0] + b0v;
            p0[HH * WW + px]     = d[mi][j][1] + b1v;
            p0[px + 8]           = d[mi][j][2] + b0v;
            p0[HH * WW + px + 8] = d[mi][j][3] + b1v;
        }
    }
}

// ============================ launch ============================
extern "C" void kernel_launch(void* const* d_in, const int* in_sizes, int n_in,
                              void* d_out, int out_size)
{
    const float* x     = (const float*)d_in[0];
    const float* alpha = (const float*)d_in[1];
    const float* wgt   = (const float*)d_in[2];
    const float* bias  = (const float*)d_in[3];
    const float* pa    = (const float*)d_in[4];
    const float* pb    = (const float*)d_in[5];
    const float* pc    = (const float*)d_in[6];
    float* out = (float*)d_out;

    wt_prepack<<<(4 * 9 * CC * 64 + 255) / 256, 256>>>(wgt);

    cudaFuncSetAttribute(conv_mma,
                         cudaFuncAttributeMaxDynamicSharedMemorySize, SMEM_BYTES);
    dim3 grid(HH / 2, BATCH);   // 64 x 4 = 256 CTAs, single wave at 2 CTA/SM
    conv_mma<<<grid, 256, SMEM_BYTES>>>(x, alpha, bias, pa, pb, pc, out);
}

// round 10
// speedup vs baseline: 2.2682x; 1.0576x over previous
#include <cuda_runtime.h>
#include <cstdint>

#define HH 128
#define WW 128
#define CHN 64
#define OCH 64
#define BATCH 4

#define CC 16            // channels per chunk (4 chunks)
#define YP 136           // y row pitch (floats); 136 % 32 == 8 -> conflict-free a-LDS
#define YOFF 4           // left pad: px p lives at YP-row offset 4+p (float4-aligned)

#define Y_FLOATS  (4 * CC * YP)             // 8704
#define W_FLOAT2  (9 * 2 * 64 * 4)          // 4608 float2 per chunk (all 9 taps)
#define W_FLOATS  (W_FLOAT2 * 2)            // 9216
#define FA_FLOATS (4 * YP)                  // 544
#define OFF_Y  0
#define OFF_W  Y_FLOATS                     // 8704 (byte 34816, 16B aligned)
#define OFF_FA (OFF_W + W_FLOATS)           // 17920
#define OFF_BI (OFF_FA + FA_FLOATS)         // 18464
#define SMEM_FLOATS (OFF_BI + 64)
#define SMEM_BYTES  (SMEM_FLOATS * 4)       // 74112 B -> 2 CTAs/SM

__device__ __forceinline__ float to_tf32(float x) {
    float r; asm("cvt.rn.tf32.f32 %0, %1;" : "=f"(r) : "f"(x)); return r;
}

__device__ __forceinline__ void mma_tf32(float* d, const uint32_t* a, uint32_t b0, uint32_t b1) {
    asm volatile(
        "mma.sync.aligned.m16n8k8.row.col.f32.tf32.tf32.f32 "
        "{%0,%1,%2,%3}, {%4,%5,%6,%7}, {%8,%9}, {%0,%1,%2,%3};\n"
        : "+f"(d[0]), "+f"(d[1]), "+f"(d[2]), "+f"(d[3])
        : "r"(a[0]), "r"(a[1]), "r"(a[2]), "r"(a[3]), "r"(b0), "r"(b1));
}

__device__ __forceinline__ void cp_async16(uint32_t s_addr, const void* g) {
    asm volatile("cp.async.cg.shared.global [%0], [%1], 16;" :: "r"(s_addr), "l"(g));
}

// ---- prepacked k-paired weights:
// g_w4[ch][t][cq][n(64)][tq(4)] float2 =
//   ( tf32(W[n][ch*16+cq*8+tq][t]), tf32(W[n][ch*16+cq*8+tq+4][t]) )
// Read side: thread lane (=4*qid+tq) for fragment j loads float2 index
// (t*2+cq)*256 + j*32 + lane  -> 32 consecutive float2 per warp, conflict-free,
// one LDS.64 = both b-operands (b0 = B[k][n], b1 = B[k+4][n]).
__device__ __align__(16) float2 g_w4[4 * W_FLOAT2];

__global__ void wt_prepack(const float* __restrict__ w) {
    int i = blockIdx.x * 256 + threadIdx.x;
    if (i >= 4 * W_FLOAT2) return;
    int tq = i & 3;
    int n  = (i >> 2) & 63;
    int cq = (i >> 8) & 1;
    int t  = (i >> 9) % 9;
    int ch = (i >> 9) / 9;
    int c0 = ch * CC + cq * 8 + tq;
    float v0 = w[(n * CHN + c0) * 9 + t];
    float v1 = w[(n * CHN + c0 + 4) * 9 + t];
    g_w4[i] = make_float2(to_tf32(v0), to_tf32(v1));
}

// ============================ main kernel ============================
// CTA = (batch, row-pair). M = 256 px, N = 64, K = 576 in 4 chunks of 16 ch.
// 8 warps, warp tile 32px x 64o. Per chunk: cp.async weight copy overlapped
// with y fill, one barrier pair; 9-tap MMA stream barrier-free.
// b-fragments via paired LDS.64: LDS instr/tap/thread 48 -> 32.

__global__ __launch_bounds__(256, 2)
void conv_mma(const float* __restrict__ x,
              const float* __restrict__ alpha,
              const float* __restrict__ bias,
              const float* __restrict__ pa,
              const float* __restrict__ pb,
              const float* __restrict__ pc,
              float* __restrict__ out)
{
    extern __shared__ float sm[];
    float*  y_s  = sm + OFF_Y;    // [4 ir][16 c][YP], px at offset YOFF+px
    float2* w2_s = (float2*)(sm + OFF_W);   // [9 t][2 cq][64 n][4 tq]
    float*  fa_s = sm + OFF_FA;   // [4 ir][YP]
    float*  bi_s = sm + OFF_BI;

    const int tid  = threadIdx.x;
    const int warp = tid >> 5;
    const int lane = tid & 31;
    const int qid  = lane >> 2;  // 0..7
    const int tq   = lane & 3;   // 0..3

    const int rp = blockIdx.x;
    const int b  = blockIdx.y;
    const int r0 = 2 * rp;

    const int lr  = warp >> 2;          // output row within pair
    const int px0 = (warp & 3) * 32;    // pixel block

    const uint32_t w_s_addr = (uint32_t)__cvta_generic_to_shared(w2_s);

    // ---- f(alpha), bias, y pad-zeros (written once)
    {
        const float A = __ldg(pa), Bq = __ldg(pb), Cq = __ldg(pc);
        const float* ap = alpha + b * HH * WW;
        for (int i = tid; i < 4 * 128; i += 256) {
            int ir = i >> 7, px = i & 127;
            int gy = r0 - 1 + ir;
            float v = 0.0f;
            if ((unsigned)gy < HH) {
                float t = __ldg(ap + gy * WW + px);
                v = (A * t + Bq) * t + Cq;
            }
            fa_s[ir * YP + YOFF + px] = v;
        }
        for (int i = tid; i < 64 * 8; i += 256) {     // zero y pads (never refilled)
            int r = i >> 3, o = i & 7;
            y_s[r * YP + (o < 4 ? o : 128 + o)] = 0.0f;
        }
        if (tid < 64) bi_s[tid] = __ldg(bias + tid);
    }

    float d[2][8][4];
    #pragma unroll
    for (int mi = 0; mi < 2; mi++)
        #pragma unroll
        for (int j = 0; j < 8; j++)
            #pragma unroll
            for (int r = 0; r < 4; r++) d[mi][j][r] = 0.0f;

    #pragma unroll 1
    for (int ch = 0; ch < 4; ch++) {
        __syncthreads();   // pads/fa ready (ch=0); prev chunk's readers done

        // ---- weights: cp.async copy of this chunk's 9-tap paired image
        {
            const char* src = (const char*)(g_w4 + ch * W_FLOAT2) + tid * 16;
            uint32_t dst = w_s_addr + tid * 16;
            #pragma unroll
            for (int i = 0; i < 9; i++)
                cp_async16(dst + i * 4096, src + i * 4096);
            asm volatile("cp.async.commit_group;" ::: "memory");
        }
        // ---- y fill: warp = one (ir,c) row per iter, float4 px-coalesced
        #pragma unroll
        for (int it = 0; it < 8; it++) {
            int r  = warp + it * 8;           // 0..63
            int ir = r >> 4, c = r & 15;
            int gy = r0 - 1 + ir;
            int px = lane * 4;
            float4 v = make_float4(0.f, 0.f, 0.f, 0.f);
            if ((unsigned)gy < HH)
                v = *(const float4*)(x + (((b * CHN + ch * CC + c) * HH) + gy) * WW + px);
            float4 f = *(const float4*)(fa_s + ir * YP + YOFF + px);
            float4 yv = make_float4(to_tf32(v.x * f.x), to_tf32(v.y * f.y),
                                    to_tf32(v.z * f.z), to_tf32(v.w * f.w));
            *(float4*)(y_s + (ir * CC + c) * YP + YOFF + px) = yv;
        }
        asm volatile("cp.async.wait_group 0;" ::: "memory");
        __syncthreads();

        // ---- 9 taps, barrier-free
        #pragma unroll 1
        for (int t = 0; t < 9; t++) {
            const int kt = t / 3, lt = t - 3 * kt;
            const float*  arow = y_s + ((lr + kt) * CC + tq) * YP + YOFF + px0 + lt - 1 + qid;
            const float2* wrow = w2_s + t * 512 + lane;

            #pragma unroll
            for (int cq = 0; cq < 2; cq++) {
                const float2* wq = wrow + cq * 256;
                float2 bv[8];
                #pragma unroll
                for (int j = 0; j < 8; j++) bv[j] = wq[j * 32];   // LDS.64, consecutive

                const float* ap = arow + cq * (8 * YP);
                uint32_t a[2][4];
                #pragma unroll
                for (int mi = 0; mi < 2; mi++) {
                    const float* p = ap + mi * 16;
                    a[mi][0] = __float_as_uint(p[0]);            // (m,   k)
                    a[mi][1] = __float_as_uint(p[8]);            // (m+8, k)
                    a[mi][2] = __float_as_uint(p[4 * YP]);       // (m,   k+4)
                    a[mi][3] = __float_as_uint(p[4 * YP + 8]);   // (m+8, k+4)
                }
                #pragma unroll
                for (int mi = 0; mi < 2; mi++)
                    #pragma unroll
                    for (int j = 0; j < 8; j++)
                        mma_tf32(d[mi][j], a[mi],
                                 __float_as_uint(bv[j].x), __float_as_uint(bv[j].y));
            }
        }
    }

    // ---- epilogue (verified fragment map)
    const int imgrow = r0 + lr;
    #pragma unroll
    for (int j = 0; j < 8; j++) {
        const int o0 = j * 8 + 2 * tq;
        const float b0v = bi_s[o0], b1v = bi_s[o0 + 1];
        float* p0 = out + (((b * OCH + o0) * HH) + imgrow) * WW;
        #pragma unroll
        for (int mi = 0; mi < 2; mi++) {
            const int px = px0 + mi * 16 + qid;
            p0[px]               = d[mi][j][0] + b0v;
            p0[HH * WW + px]     = d[mi][j][1] + b1v;
            p0[px + 8]           = d[mi][j][2] + b0v;
            p0[HH * WW + px + 8] = d[mi][j][3] + b1v;
        }
    }
}

// ============================ launch ============================
extern "C" void kernel_launch(void* const* d_in, const int* in_sizes, int n_in,
                              void* d_out, int out_size)
{
    const float* x     = (const float*)d_in[0];
    const float* alpha = (const float*)d_in[1];
    const float* wgt   = (const float*)d_in[2];
    const float* bias  = (const float*)d_in[3];
    const float* pa    = (const float*)d_in[4];
    const float* pb    = (const float*)d_in[5];
    const float* pc    = (const float*)d_in[6];
    float* out = (float*)d_out;

    wt_prepack<<<(4 * W_FLOAT2 + 255) / 256, 256>>>(wgt);

    cudaFuncSetAttribute(conv_mma,
                         cudaFuncAttributeMaxDynamicSharedMemorySize, SMEM_BYTES);
    dim3 grid(HH / 2, BATCH);   // 64 x 4 = 256 CTAs, single wave at 2 CTA/SM
    conv_mma<<<grid, 256, SMEM_BYTES>>>(x, alpha, bias, pa, pb, pc, out);
}